// round 1
// baseline (speedup 1.0000x reference)
#include <cuda_runtime.h>
#include <cstdint>

#define B_  8
#define C_  256
#define N_  4096
#define CQ_ 32

typedef unsigned long long ull;

// Scratch (allocation-free rule: __device__ globals)
__device__ float g_q[B_ * N_ * CQ_];              // [B][N][32]
__device__ float g_k[B_ * N_ * CQ_];              // [B][N][32]
__device__ float g_v[B_ * N_ * C_];               // [B][N][256]

// ---------------- packed f32x2 helpers (sm_100+ PTX) ----------------
__device__ __forceinline__ ull ffma2(ull a, ull b, ull c) {
    ull d;
    asm("fma.rn.f32x2 %0, %1, %2, %3;" : "=l"(d) : "l"(a), "l"(b), "l"(c));
    return d;
}
__device__ __forceinline__ ull mul2(ull a, ull b) {
    ull d;
    asm("mul.rn.f32x2 %0, %1, %2;" : "=l"(d) : "l"(a), "l"(b));
    return d;
}
__device__ __forceinline__ ull pack2(float x, float y) {
    ull r;
    asm("mov.b64 %0, {%1, %2};" : "=l"(r) : "f"(x), "f"(y));
    return r;
}
__device__ __forceinline__ float2 unpack2(ull v) {
    float2 f;
    asm("mov.b64 {%0, %1}, %2;" : "=f"(f.x), "=f"(f.y) : "l"(v));
    return f;
}

// ====================================================================
// Projection kernel: q/k/v = W @ x  (+bias), per 64-column tile of x.
// block: 256 thr; thread t: n = t&63 (column), grp = t>>6 (output group)
// grp owns 64 v-channels (as 32 f32x2 pairs) + 8 q-dims + 8 k-dims.
// Weights staged in SMEM transposed ([ci][co]) so reads are ull broadcasts.
// ====================================================================
#define PROJ_SMEM_FLOATS (2048 + 32*258 + 32*36 + 32*36)
#define PROJ_SMEM_BYTES  (PROJ_SMEM_FLOATS * 4)

__global__ void __launch_bounds__(256) proj_kernel(
    const float* __restrict__ x,
    const float* __restrict__ wq, const float* __restrict__ bq,
    const float* __restrict__ wk, const float* __restrict__ bk,
    const float* __restrict__ wv, const float* __restrict__ bv)
{
    extern __shared__ float sm[];
    float* xs  = sm;                 // [32][64]
    float* wvs = sm + 2048;          // [ci:32][co:258pad]
    float* wqs = wvs + 32 * 258;     // [ci:32][d:36pad]
    float* wks = wqs + 32 * 36;      // [ci:32][d:36pad]

    const int tid = threadIdx.x;
    const int n   = tid & 63;
    const int grp = tid >> 6;        // 0..3
    const int b   = blockIdx.y;
    const int n0  = blockIdx.x * 64;

    ull accv[32];
    ull accq[4], acck[4];
#pragma unroll
    for (int i = 0; i < 32; i++) accv[i] = 0ull;
#pragma unroll
    for (int i = 0; i < 4; i++) { accq[i] = 0ull; acck[i] = 0ull; }

    for (int kc = 0; kc < 8; kc++) {           // 8 chunks of 32 input channels
        __syncthreads();
        // x chunk [32ci][64n]
        {
            const float4* xg = (const float4*)(x + ((size_t)b * C_ + kc * 32) * N_ + n0);
            float4* xs4 = (float4*)xs;
            for (int i = tid; i < 32 * 16; i += 256) {
                int ci = i >> 4, n4 = i & 15;
                xs4[ci * 16 + n4] = xg[(size_t)ci * (N_ / 4) + n4];
            }
        }
        // wv chunk transposed: wvs[ci*258 + co]
        for (int i = tid; i < 256 * 32; i += 256) {
            int co = i >> 5, ci = i & 31;
            wvs[ci * 258 + co] = wv[co * C_ + kc * 32 + ci];
        }
        // wq/wk chunk transposed
        for (int i = tid; i < 32 * 32; i += 256) {
            int d = i >> 5, ci = i & 31;
            wqs[ci * 36 + d] = wq[d * C_ + kc * 32 + ci];
            wks[ci * 36 + d] = wk[d * C_ + kc * 32 + ci];
        }
        __syncthreads();

#pragma unroll 4
        for (int ci = 0; ci < 32; ci++) {
            float xv = xs[ci * 64 + n];
            ull  xv2 = pack2(xv, xv);
            const ull* wr  = (const ull*)&wvs[ci * 258 + grp * 64];
#pragma unroll
            for (int i = 0; i < 32; i++)
                accv[i] = ffma2(wr[i], xv2, accv[i]);
            const ull* wrq = (const ull*)&wqs[ci * 36 + grp * 8];
            const ull* wrk = (const ull*)&wks[ci * 36 + grp * 8];
#pragma unroll
            for (int i = 0; i < 4; i++) {
                accq[i] = ffma2(wrq[i], xv2, accq[i]);
                acck[i] = ffma2(wrk[i], xv2, acck[i]);
            }
        }
    }

    const size_t ng = (size_t)b * N_ + n0 + n;
    // store V [B][N][256]
    {
        float4* vout = (float4*)(g_v + ng * C_ + grp * 64);
#pragma unroll
        for (int i = 0; i < 16; i++) {
            float2 a  = unpack2(accv[2 * i]);
            float2 b2 = unpack2(accv[2 * i + 1]);
            float4 o;
            o.x = a.x  + __ldg(&bv[grp * 64 + 4 * i + 0]);
            o.y = a.y  + __ldg(&bv[grp * 64 + 4 * i + 1]);
            o.z = b2.x + __ldg(&bv[grp * 64 + 4 * i + 2]);
            o.w = b2.y + __ldg(&bv[grp * 64 + 4 * i + 3]);
            vout[i] = o;
        }
    }
    // store Q/K [B][N][32]
    {
        float4* qout = (float4*)(g_q + ng * CQ_ + grp * 8);
        float4* kout = (float4*)(g_k + ng * CQ_ + grp * 8);
#pragma unroll
        for (int i = 0; i < 2; i++) {
            float2 a  = unpack2(accq[2 * i]);
            float2 b2 = unpack2(accq[2 * i + 1]);
            float4 o;
            o.x = a.x  + __ldg(&bq[grp * 8 + 4 * i + 0]);
            o.y = a.y  + __ldg(&bq[grp * 8 + 4 * i + 1]);
            o.z = b2.x + __ldg(&bq[grp * 8 + 4 * i + 2]);
            o.w = b2.y + __ldg(&bq[grp * 8 + 4 * i + 3]);
            qout[i] = o;
            a  = unpack2(acck[2 * i]);
            b2 = unpack2(acck[2 * i + 1]);
            float4 ok;
            ok.x = a.x  + __ldg(&bk[grp * 8 + 4 * i + 0]);
            ok.y = a.y  + __ldg(&bk[grp * 8 + 4 * i + 1]);
            ok.z = b2.x + __ldg(&bk[grp * 8 + 4 * i + 2]);
            ok.w = b2.y + __ldg(&bk[grp * 8 + 4 * i + 3]);
            kout[i] = ok;
        }
    }
}

// ====================================================================
// Flash-attention kernel: 64 queries/block, 64-key tiles, online softmax.
// PV: thread (qg = t>>5, cg = t&31) accumulates 8 queries x 4 f32x2 channel
// pairs; pair i covers channels {64*i + 2*cg, +1} -> contiguous LDS.64 V reads.
// ====================================================================
#define SQ_  0                       // qs [64][36]
#define SK_  (64 * 36)               // ks [64][32]
#define SV_  (SK_ + 64 * 32)         // vs [64][256]
#define SE_  (SV_ + 64 * 256)        // es [64][65]
#define SMX_ (SE_ + 64 * 65)         // row max [64]
#define SCF_ (SMX_ + 64)             // correction factor [64]
#define SL_  (SCF_ + 64)             // row sum [64]
#define SPS_ (SL_ + 64)              // partial sums [64][4]
#define ATTN_SMEM_FLOATS (SPS_ + 256)
#define ATTN_SMEM_BYTES  (ATTN_SMEM_FLOATS * 4)

__global__ void __launch_bounds__(256, 2) attn_kernel(
    const float* __restrict__ x, float* __restrict__ out)
{
    extern __shared__ float sm[];
    const int tid = threadIdx.x;
    const int b   = blockIdx.y;
    const int q0  = blockIdx.x * 64;

    // load Q tile into SMEM (padded rows of 36)
    for (int i = tid; i < 64 * 32; i += 256) {
        int q = i >> 5, d = i & 31;
        sm[SQ_ + q * 36 + d] = g_q[((size_t)b * N_ + q0 + q) * CQ_ + d];
    }
    if (tid < 64) { sm[SMX_ + tid] = -1e30f; sm[SL_ + tid] = 0.f; }

    const int qrow = tid & 63;       // energy-phase row
    const int jgrp = tid >> 6;       // energy-phase j group (0..3)
    const int qg   = tid >> 5;       // PV query group (0..7)
    const int cg   = tid & 31;       // PV channel lane

    ull acc[8][4];
#pragma unroll
    for (int r = 0; r < 8; r++)
#pragma unroll
        for (int i = 0; i < 4; i++) acc[r][i] = 0ull;

    for (int t = 0; t < 64; t++) {
        const int j0 = t * 64;
        __syncthreads();                       // vs/ks safe to overwrite
        {
            const float4* kg = (const float4*)(g_k + ((size_t)b * N_ + j0) * CQ_);
            float4* ks4 = (float4*)&sm[SK_];
            for (int i = tid; i < 512; i += 256) ks4[i] = kg[i];
            const float4* vg = (const float4*)(g_v + ((size_t)b * N_ + j0) * C_);
            float4* vs4 = (float4*)&sm[SV_];
            for (int i = tid; i < 4096; i += 256) vs4[i] = vg[i];
        }
        __syncthreads();
        // ---- energy: e[q][j] = <q_row, k_row> ----
        {
            const float4* qv = (const float4*)&sm[SQ_ + qrow * 36];
#pragma unroll 2
            for (int jj = 0; jj < 16; jj++) {
                int j = jgrp * 16 + jj;
                const float4* kv = (const float4*)&sm[SK_ + j * 32];
                float e = 0.f;
#pragma unroll
                for (int d4 = 0; d4 < 8; d4++) {
                    float4 qq = qv[d4];
                    float4 kk = kv[d4];
                    e += qq.x * kk.x + qq.y * kk.y + qq.z * kk.z + qq.w * kk.w;
                }
                sm[SE_ + qrow * 65 + j] = e;
            }
        }
        __syncthreads();
        // ---- row max + correction factor ----
        if (tid < 64) {
            float mold = sm[SMX_ + tid];
            float mx = mold;
#pragma unroll 8
            for (int j = 0; j < 64; j++) mx = fmaxf(mx, sm[SE_ + tid * 65 + j]);
            sm[SMX_ + tid] = mx;
            sm[SCF_ + tid] = __expf(mold - mx);
        }
        __syncthreads();
        // ---- exponentiate + partial sums + rescale accumulators ----
        {
            float Mn = sm[SMX_ + qrow];
            float s = 0.f;
#pragma unroll 4
            for (int jj = 0; jj < 16; jj++) {
                int j = jgrp * 16 + jj;
                float p = __expf(sm[SE_ + qrow * 65 + j] - Mn);
                sm[SE_ + qrow * 65 + j] = p;
                s += p;
            }
            sm[SPS_ + qrow * 4 + jgrp] = s;
#pragma unroll
            for (int r = 0; r < 8; r++) {
                float cf = sm[SCF_ + qg * 8 + r];
                ull cf2 = pack2(cf, cf);
#pragma unroll
                for (int i = 0; i < 4; i++) acc[r][i] = mul2(acc[r][i], cf2);
            }
        }
        __syncthreads();
        // ---- row-sum update + PV accumulation ----
        if (tid < 64) {
            sm[SL_ + tid] = sm[SL_ + tid] * sm[SCF_ + tid]
                + sm[SPS_ + tid * 4 + 0] + sm[SPS_ + tid * 4 + 1]
                + sm[SPS_ + tid * 4 + 2] + sm[SPS_ + tid * 4 + 3];
        }
        {
            const float* pbase = &sm[SE_ + (qg * 8) * 65];
            const ull* vbase = (const ull*)&sm[SV_];
#pragma unroll 2
            for (int j = 0; j < 64; j++) {
                ull v0 = vbase[j * 128 + 0 * 32 + cg];
                ull v1 = vbase[j * 128 + 1 * 32 + cg];
                ull v2 = vbase[j * 128 + 2 * 32 + cg];
                ull v3 = vbase[j * 128 + 3 * 32 + cg];
#pragma unroll
                for (int r = 0; r < 8; r++) {
                    float p = pbase[r * 65 + j];
                    ull p2 = pack2(p, p);
                    acc[r][0] = ffma2(v0, p2, acc[r][0]);
                    acc[r][1] = ffma2(v1, p2, acc[r][1]);
                    acc[r][2] = ffma2(v2, p2, acc[r][2]);
                    acc[r][3] = ffma2(v3, p2, acc[r][3]);
                }
            }
        }
    }
    __syncthreads();
    // ---- epilogue: out = x + acc / l ----
#pragma unroll
    for (int r = 0; r < 8; r++) {
        const int q = q0 + qg * 8 + r;
        const float inv = 1.0f / sm[SL_ + qg * 8 + r];
#pragma unroll
        for (int i = 0; i < 4; i++) {
            float2 a = unpack2(acc[r][i]);
            const int c0 = i * 64 + 2 * cg;
            size_t o = ((size_t)b * C_ + c0) * N_ + q;
            out[o]      = fmaf(a.x, inv, x[o]);
            out[o + N_] = fmaf(a.y, inv, x[o + N_]);
        }
    }
}

// ====================================================================
extern "C" void kernel_launch(void* const* d_in, const int* in_sizes, int n_in,
                              void* d_out, int out_size)
{
    const float* x  = (const float*)d_in[0];
    const float* wq = (const float*)d_in[1];
    const float* bq = (const float*)d_in[2];
    const float* wk = (const float*)d_in[3];
    const float* bk = (const float*)d_in[4];
    const float* wv = (const float*)d_in[5];
    const float* bv = (const float*)d_in[6];
    float* out = (float*)d_out;

    cudaFuncSetAttribute(proj_kernel, cudaFuncAttributeMaxDynamicSharedMemorySize, PROJ_SMEM_BYTES);
    cudaFuncSetAttribute(attn_kernel, cudaFuncAttributeMaxDynamicSharedMemorySize, ATTN_SMEM_BYTES);

    proj_kernel<<<dim3(N_ / 64, B_), 256, PROJ_SMEM_BYTES>>>(x, wq, bq, wk, bk, wv, bv);
    attn_kernel<<<dim3(N_ / 64, B_), 256, ATTN_SMEM_BYTES>>>(x, out);
}